// round 2
// baseline (speedup 1.0000x reference)
#include <cuda_runtime.h>
#include <cstddef>

#define EMB 256
#define HID 128
#define N_REL 10

// Scratch: per-node projections P[n][0:128] = emb@W1, P[n][128:256] = emb@W2
__device__ float g_P[(size_t)100000 * 256];
__device__ float g_Qh[N_REL * HID];

__device__ __forceinline__ unsigned long long dup2(float a) {
    unsigned long long r;
    unsigned int u = __float_as_uint(a);
    asm("mov.b64 %0, {%1, %1};" : "=l"(r) : "r"(u));
    return r;
}
__device__ __forceinline__ void fma2(unsigned long long& d, unsigned long long a, unsigned long long b) {
    asm("fma.rn.f32x2 %0, %1, %2, %0;" : "+l"(d) : "l"(a), "l"(b));
}
__device__ __forceinline__ float lo32(unsigned long long v) { return __uint_as_float((unsigned)v); }
__device__ __forceinline__ float hi32(unsigned long long v) { return __uint_as_float((unsigned)(v >> 32)); }

// ---------------------------------------------------------------------------
// Kernel 1: Qh[r][c] = b_q[c] + sum_t rel_emb[r][t] * W_q[t][c]   (10x128)
// ---------------------------------------------------------------------------
__global__ void qh_kernel(const float* __restrict__ rel_emb,
                          const float* __restrict__ W_q,
                          const float* __restrict__ b_q) {
    int idx = blockIdx.x * 256 + threadIdx.x;
    if (idx < N_REL * HID) {
        int r = idx >> 7, c = idx & 127;
        float s = b_q[c];
#pragma unroll 16
        for (int t = 0; t < 64; t++) s = fmaf(rel_emb[r * 64 + t], W_q[t * 128 + c], s);
        g_Qh[idx] = s;
    }
}

// ---------------------------------------------------------------------------
// Kernel 2: node projections. grid = (ceil(N/64), 2). cb=0 -> W rows [0,256),
// cb=1 -> W rows [256,512). Tile: 64 nodes x 128 cols, K-chunks of 32.
// ---------------------------------------------------------------------------
__global__ __launch_bounds__(256) void nodeproj_kernel(const float* __restrict__ emb,
                                                       const float* __restrict__ W_edge,
                                                       int n_nodes) {
    __shared__ float sA[64 * 32];
    __shared__ float sW[32 * 128];
    int tid = threadIdx.x;
    int tx = tid & 15, ty = tid >> 4;
    int n0 = blockIdx.x * 64;
    int cb = blockIdx.y;
    const float* Wbase = W_edge + (size_t)cb * 256 * 128;

    unsigned long long acc[4][4];
#pragma unroll
    for (int i = 0; i < 4; i++)
#pragma unroll
        for (int j = 0; j < 4; j++) acc[i][j] = 0ull;

    for (int k0 = 0; k0 < 256; k0 += 32) {
        __syncthreads();
        {
            int row = tid >> 2, q = tid & 3;
            int n = n0 + row; if (n >= n_nodes) n = n_nodes - 1;
            const float4* np = (const float4*)(emb + (size_t)n * EMB + k0);
            float4* dst = (float4*)(sA + row * 32);
            dst[q]     = np[q];
            dst[q + 4] = np[q + 4];
            const float4* wp = (const float4*)(Wbase + (size_t)k0 * 128);
            float4* dw = (float4*)sW;
#pragma unroll
            for (int u = 0; u < 4; u++) dw[tid + u * 256] = wp[tid + u * 256];
        }
        __syncthreads();
#pragma unroll 8
        for (int kk = 0; kk < 32; kk++) {
            unsigned long long w[4];
#pragma unroll
            for (int j = 0; j < 4; j++)
                w[j] = *(const unsigned long long*)(sW + kk * 128 + j * 32 + 2 * tx);
#pragma unroll
            for (int i = 0; i < 4; i++) {
                unsigned long long a2 = dup2(sA[(ty * 4 + i) * 32 + kk]);
#pragma unroll
                for (int j = 0; j < 4; j++) fma2(acc[i][j], a2, w[j]);
            }
        }
    }
#pragma unroll
    for (int i = 0; i < 4; i++) {
        int n = n0 + ty * 4 + i;
        if (n < n_nodes) {
#pragma unroll
            for (int j = 0; j < 4; j++)
                *(unsigned long long*)(g_P + (size_t)n * 256 + cb * 128 + j * 32 + 2 * tx) = acc[i][j];
        }
    }
}

// ---------------------------------------------------------------------------
// Kernel 3: per-edge pipeline. 64 edges/block, 256 threads.
// Microtile: thread (tx,ty) owns edges ty*4..ty*4+3, column pairs c=j*32+2*tx.
// ---------------------------------------------------------------------------
__device__ __forceinline__ void hs_gemm(const float* __restrict__ Wg,
                                        const float* __restrict__ bg,
                                        float* sW, const float* hs,
                                        int tid, int tx, int ty,
                                        unsigned long long acc[4][4]) {
#pragma unroll
    for (int j = 0; j < 4; j++) {
        unsigned long long b = *(const unsigned long long*)(bg + j * 32 + 2 * tx);
#pragma unroll
        for (int i = 0; i < 4; i++) acc[i][j] = b;
    }
    for (int k0 = 0; k0 < 128; k0 += 32) {
        __syncthreads();
        const float4* wp = (const float4*)(Wg + (size_t)k0 * 128);
        float4* dw = (float4*)sW;
#pragma unroll
        for (int u = 0; u < 4; u++) dw[tid + u * 256] = wp[tid + u * 256];
        __syncthreads();
#pragma unroll 8
        for (int kk = 0; kk < 32; kk++) {
            unsigned long long w[4];
#pragma unroll
            for (int j = 0; j < 4; j++)
                w[j] = *(const unsigned long long*)(sW + kk * 128 + j * 32 + 2 * tx);
#pragma unroll
            for (int i = 0; i < 4; i++) {
                unsigned long long a2 = dup2(hs[(ty * 4 + i) * 128 + k0 + kk]);
#pragma unroll
                for (int j = 0; j < 4; j++) fma2(acc[i][j], a2, w[j]);
            }
        }
    }
}

__global__ __launch_bounds__(256) void edge_kernel(
    const int* __restrict__ edge_index, const int* __restrict__ rel_type,
    const float* __restrict__ b_edge,
    const float* __restrict__ W_k, const float* __restrict__ b_k,
    const float* __restrict__ W_v, const float* __restrict__ b_v,
    const float* __restrict__ W_o1, const float* __restrict__ b_o1,
    const float* __restrict__ W_o2, const float* __restrict__ b_o2,
    float* __restrict__ out, int E) {
    extern __shared__ float smem[];
    float* hs  = smem;                 // 64*128
    float* sW  = hs + 64 * 128;        // 32*128
    float* sQh = sW + 32 * 128;        // 1280
    float* sSc = sQh + 1280;           // 256
    int* sSrc = (int*)(sSc + 256);     // 64
    int* sTgt = sSrc + 64;             // 64
    int* sRel = sTgt + 64;             // 64

    int tid = threadIdx.x;
    int tx = tid & 15, ty = tid >> 4;
    int e0 = blockIdx.x * 64;

    for (int u = tid; u < N_REL * HID; u += 256) sQh[u] = g_Qh[u];
    if (tid < 64) {
        int e = e0 + tid;
        int eg = e < E ? e : E - 1;
        sSrc[tid] = edge_index[eg];
        sTgt[tid] = edge_index[E + eg];
        sRel[tid] = rel_type[eg];
    }
    __syncthreads();

    // hs = relu(P[src][0:128] + P[tgt][128:256] + b_edge)
    // 4 threads per row; each writes 8 float4s (32 floats) -> full 128 cols.
    {
        int row = tid >> 2, q = tid & 3;
        const float4* ps = (const float4*)(g_P + (size_t)sSrc[row] * 256);
        const float4* pt = (const float4*)(g_P + (size_t)sTgt[row] * 256 + 128);
        const float4* bb = (const float4*)b_edge;
        float4* hd = (float4*)(hs + row * 128);
#pragma unroll
        for (int u = 0; u < 8; u++) {
            int idx = q + u * 4;
            float4 a = ps[idx], b = pt[idx], c = bb[idx];
            float4 r;
            r.x = fmaxf(a.x + b.x + c.x, 0.f);
            r.y = fmaxf(a.y + b.y + c.y, 0.f);
            r.z = fmaxf(a.z + b.z + c.z, 0.f);
            r.w = fmaxf(a.w + b.w + c.w, 0.f);
            hd[idx] = r;
        }
    }

    unsigned long long acc[4][4];

    // ---- K pass + per-head Q.K scores ----
    hs_gemm(W_k, b_k, sW, hs, tid, tx, ty, acc);
#pragma unroll
    for (int i = 0; i < 4; i++) {
        int e = ty * 4 + i;
        const float* q = sQh + sRel[e] * 128;
        float p[4];
#pragma unroll
        for (int j = 0; j < 4; j++) {
            int c = j * 32 + 2 * tx;
            p[j] = lo32(acc[i][j]) * q[c] + hi32(acc[i][j]) * q[c + 1];
        }
#pragma unroll
        for (int m = 1; m < 16; m <<= 1) {
#pragma unroll
            for (int j = 0; j < 4; j++) p[j] += __shfl_xor_sync(0xffffffffu, p[j], m);
        }
        if (tx == 0) {
#pragma unroll
            for (int j = 0; j < 4; j++) sSc[e * 4 + j] = p[j] * 0.17677669529663687f; // 1/sqrt(32)
        }
    }

    // ---- V pass (internal syncthreads make sSc visible to all) ----
    hs_gemm(W_v, b_v, sW, hs, tid, tx, ty, acc);
    __syncthreads();  // all hs reads done before in-place update

    // softmax over 4 heads; out = hs + attn*V, written in place
#pragma unroll
    for (int i = 0; i < 4; i++) {
        int e = ty * 4 + i;
        float s0 = sSc[e * 4 + 0], s1 = sSc[e * 4 + 1], s2 = sSc[e * 4 + 2], s3 = sSc[e * 4 + 3];
        float mx = fmaxf(fmaxf(s0, s1), fmaxf(s2, s3));
        float x0 = __expf(s0 - mx), x1 = __expf(s1 - mx), x2 = __expf(s2 - mx), x3 = __expf(s3 - mx);
        float inv = 1.f / (x0 + x1 + x2 + x3);
        float at[4] = {x0 * inv, x1 * inv, x2 * inv, x3 * inv};
#pragma unroll
        for (int j = 0; j < 4; j++) {
            int c = j * 32 + 2 * tx;
            float2 h2 = *(float2*)(hs + e * 128 + c);
            h2.x += at[j] * lo32(acc[i][j]);
            h2.y += at[j] * hi32(acc[i][j]);
            *(float2*)(hs + e * 128 + c) = h2;
        }
    }

    // ---- O1 pass, relu, dot with W_o2, reduce, store ----
    hs_gemm(W_o1, b_o1, sW, hs, tid, tx, ty, acc);
    float bo2 = __ldg(b_o2);
#pragma unroll
    for (int i = 0; i < 4; i++) {
        float p = 0.f;
#pragma unroll
        for (int j = 0; j < 4; j++) {
            int c = j * 32 + 2 * tx;
            p = fmaf(fmaxf(lo32(acc[i][j]), 0.f), __ldg(W_o2 + c), p);
            p = fmaf(fmaxf(hi32(acc[i][j]), 0.f), __ldg(W_o2 + c + 1), p);
        }
#pragma unroll
        for (int m = 1; m < 16; m <<= 1) p += __shfl_xor_sync(0xffffffffu, p, m);
        if (tx == 0) {
            int e = e0 + ty * 4 + i;
            if (e < E) out[e] = p + bo2;
        }
    }
}

// ---------------------------------------------------------------------------
extern "C" void kernel_launch(void* const* d_in, const int* in_sizes, int n_in,
                              void* d_out, int out_size) {
    const float* node_emb = (const float*)d_in[0];
    const int*   edge_index = (const int*)d_in[1];
    const int*   rel_type = (const int*)d_in[2];
    const float* rel_emb = (const float*)d_in[3];
    const float* W_edge = (const float*)d_in[4];
    const float* b_edge = (const float*)d_in[5];
    const float* W_q = (const float*)d_in[6];
    const float* b_q = (const float*)d_in[7];
    const float* W_k = (const float*)d_in[8];
    const float* b_k = (const float*)d_in[9];
    const float* W_v = (const float*)d_in[10];
    const float* b_v = (const float*)d_in[11];
    const float* W_o1 = (const float*)d_in[12];
    const float* b_o1 = (const float*)d_in[13];
    const float* W_o2 = (const float*)d_in[14];
    const float* b_o2 = (const float*)d_in[15];
    float* out = (float*)d_out;

    int n_nodes = in_sizes[0] / EMB;   // 100000
    int E = in_sizes[2];               // 500000

    qh_kernel<<<(N_REL * HID + 255) / 256, 256>>>(rel_emb, W_q, b_q);

    dim3 g2((n_nodes + 63) / 64, 2);
    nodeproj_kernel<<<g2, 256>>>(node_emb, W_edge, n_nodes);

    const int SMEM3 = (64 * 128 + 32 * 128 + 1280 + 256) * 4 + 3 * 64 * 4;  // 56064 B
    cudaFuncSetAttribute(edge_kernel, cudaFuncAttributeMaxDynamicSharedMemorySize, SMEM3);
    edge_kernel<<<(E + 63) / 64, 256, SMEM3>>>(
        edge_index, rel_type, b_edge, W_k, b_k, W_v, b_v,
        W_o1, b_o1, W_o2, b_o2, out, E);
}

// round 3
// speedup vs baseline: 1.1484x; 1.1484x over previous
#include <cuda_runtime.h>
#include <cstddef>

#define EMB 256
#define HID 128
#define N_REL 10

// Scratch
__device__ float g_P[(size_t)100000 * 256];   // per-node projections
__device__ float g_M[N_REL * 128 * 4];        // m[r][k][h]
__device__ float g_C[N_REL * 4];              // c[r][h]

__device__ __forceinline__ unsigned long long dup2(float a) {
    unsigned long long r;
    unsigned int u = __float_as_uint(a);
    asm("mov.b64 %0, {%1, %1};" : "=l"(r) : "r"(u));
    return r;
}
__device__ __forceinline__ void fma2(unsigned long long& d, unsigned long long a, unsigned long long b) {
    asm("fma.rn.f32x2 %0, %1, %2, %0;" : "+l"(d) : "l"(a), "l"(b));
}
__device__ __forceinline__ float lo32(unsigned long long v) { return __uint_as_float((unsigned)v); }
__device__ __forceinline__ float hi32(unsigned long long v) { return __uint_as_float((unsigned)(v >> 32)); }

// ---------------------------------------------------------------------------
// Prep: Qh[r] = rel_emb[r]@W_q + b_q, then fold through W_k / b_k:
//   m[r][k][h] = sum_{d<32} W_k[k][h*32+d] * Qh[r][h*32+d]
//   c[r][h]    = sum_{d<32} b_k[h*32+d]    * Qh[r][h*32+d]
// grid = N_REL blocks, 128 threads.
// ---------------------------------------------------------------------------
__global__ void prep_kernel(const float* __restrict__ rel_emb,
                            const float* __restrict__ W_q,
                            const float* __restrict__ b_q,
                            const float* __restrict__ W_k,
                            const float* __restrict__ b_k) {
    __shared__ float qh[128];
    int r = blockIdx.x;
    int c = threadIdx.x;
    float s = b_q[c];
#pragma unroll 16
    for (int t = 0; t < 64; t++) s = fmaf(rel_emb[r * 64 + t], W_q[t * 128 + c], s);
    qh[c] = s;
    __syncthreads();

    int k = threadIdx.x;
    float m[4] = {0.f, 0.f, 0.f, 0.f};
#pragma unroll 8
    for (int d = 0; d < 32; d++) {
#pragma unroll
        for (int h = 0; h < 4; h++)
            m[h] = fmaf(W_k[k * 128 + h * 32 + d], qh[h * 32 + d], m[h]);
    }
    float4 m4 = {m[0], m[1], m[2], m[3]};
    *(float4*)(g_M + r * 512 + k * 4) = m4;

    if (k < 4) {
        float cc = 0.f;
#pragma unroll 8
        for (int d = 0; d < 32; d++) cc = fmaf(b_k[k * 32 + d], qh[k * 32 + d], cc);
        g_C[r * 4 + k] = cc;
    }
}

// ---------------------------------------------------------------------------
// Node projections. grid = (ceil(N/128), 2). cb selects W rows [0,256)/[256,512).
// Tile: 128 nodes x 128 cols, K-chunks of 32, thread owns 8 rows x 4 col-pairs.
// ---------------------------------------------------------------------------
__global__ __launch_bounds__(256, 2) void nodeproj_kernel(const float* __restrict__ emb,
                                                          const float* __restrict__ W_edge,
                                                          int n_nodes) {
    __shared__ float sA[128 * 32];
    __shared__ float sW[32 * 128];
    int tid = threadIdx.x;
    int tx = tid & 15, ty = tid >> 4;
    int n0 = blockIdx.x * 128;
    int cb = blockIdx.y;
    const float* Wbase = W_edge + (size_t)cb * 256 * 128;

    unsigned long long acc[8][4];
#pragma unroll
    for (int i = 0; i < 8; i++)
#pragma unroll
        for (int j = 0; j < 4; j++) acc[i][j] = 0ull;

    for (int k0 = 0; k0 < 256; k0 += 32) {
        __syncthreads();
        {
            int row = tid >> 1, q = tid & 1;
            int n = n0 + row; if (n >= n_nodes) n = n_nodes - 1;
            const float4* np = (const float4*)(emb + (size_t)n * EMB + k0);
            float4* dst = (float4*)(sA + row * 32);
#pragma unroll
            for (int u = 0; u < 4; u++) dst[q + u * 2] = np[q + u * 2];
            const float4* wp = (const float4*)(Wbase + (size_t)k0 * 128);
            float4* dw = (float4*)sW;
#pragma unroll
            for (int u = 0; u < 4; u++) dw[tid + u * 256] = wp[tid + u * 256];
        }
        __syncthreads();
#pragma unroll 8
        for (int kk = 0; kk < 32; kk++) {
            unsigned long long w[4];
#pragma unroll
            for (int j = 0; j < 4; j++)
                w[j] = *(const unsigned long long*)(sW + kk * 128 + j * 32 + 2 * tx);
#pragma unroll
            for (int i = 0; i < 8; i++) {
                unsigned long long a2 = dup2(sA[(ty * 8 + i) * 32 + kk]);
#pragma unroll
                for (int j = 0; j < 4; j++) fma2(acc[i][j], a2, w[j]);
            }
        }
    }
#pragma unroll
    for (int i = 0; i < 8; i++) {
        int n = n0 + ty * 8 + i;
        if (n < n_nodes) {
#pragma unroll
            for (int j = 0; j < 4; j++)
                *(unsigned long long*)(g_P + (size_t)n * 256 + cb * 128 + j * 32 + 2 * tx) = acc[i][j];
        }
    }
}

// ---------------------------------------------------------------------------
// Edge kernel: 128 edges/block, 256 threads. Thread (tx,ty) owns edges
// ty*8..ty*8+7, column pairs c = j*32 + 2*tx.
// ---------------------------------------------------------------------------
__device__ __forceinline__ void hs_gemm8(const float* __restrict__ Wg,
                                         const float* __restrict__ bg,
                                         float* sW, const float* hs,
                                         int tid, int tx, int ty,
                                         unsigned long long acc[8][4]) {
#pragma unroll
    for (int j = 0; j < 4; j++) {
        unsigned long long b = *(const unsigned long long*)(bg + j * 32 + 2 * tx);
#pragma unroll
        for (int i = 0; i < 8; i++) acc[i][j] = b;
    }
    for (int k0 = 0; k0 < 128; k0 += 32) {
        __syncthreads();
        const float4* wp = (const float4*)(Wg + (size_t)k0 * 128);
        float4* dw = (float4*)sW;
#pragma unroll
        for (int u = 0; u < 4; u++) dw[tid + u * 256] = wp[tid + u * 256];
        __syncthreads();
#pragma unroll 8
        for (int kk = 0; kk < 32; kk++) {
            unsigned long long w[4];
#pragma unroll
            for (int j = 0; j < 4; j++)
                w[j] = *(const unsigned long long*)(sW + kk * 128 + j * 32 + 2 * tx);
#pragma unroll
            for (int i = 0; i < 8; i++) {
                unsigned long long a2 = dup2(hs[(ty * 8 + i) * 128 + k0 + kk]);
#pragma unroll
                for (int j = 0; j < 4; j++) fma2(acc[i][j], a2, w[j]);
            }
        }
    }
}

__global__ __launch_bounds__(256, 2) void edge_kernel(
    const int* __restrict__ edge_index, const int* __restrict__ rel_type,
    const float* __restrict__ b_edge,
    const float* __restrict__ W_v, const float* __restrict__ b_v,
    const float* __restrict__ W_o1, const float* __restrict__ b_o1,
    const float* __restrict__ W_o2, const float* __restrict__ b_o2,
    float* __restrict__ out, int E) {
    extern __shared__ float smem[];
    float* hs  = smem;                  // 128*128 = 16384
    float* sW  = hs + 128 * 128;        // 32*128  = 4096
    float* sM  = sW + 32 * 128;         // 10*512  = 5120
    float* sC  = sM + N_REL * 512;      // 40
    float* sSc = sC + N_REL * 4;        // 512
    int* sSrc = (int*)(sSc + 512);      // 128
    int* sTgt = sSrc + 128;             // 128
    int* sRel = sTgt + 128;             // 128

    int tid = threadIdx.x;
    int tx = tid & 15, ty = tid >> 4;
    int e0 = blockIdx.x * 128;

    for (int u = tid; u < N_REL * 512; u += 256) sM[u] = g_M[u];
    if (tid < N_REL * 4) sC[tid] = g_C[tid];
    if (tid < 128) {
        int e = e0 + tid;
        int eg = e < E ? e : E - 1;
        sSrc[tid] = edge_index[eg];
        sTgt[tid] = edge_index[E + eg];
        sRel[tid] = rel_type[eg];
    }
    __syncthreads();

    // hs = relu(P[src][0:128] + P[tgt][128:256] + b_edge); 2 threads per row.
    {
        int row = tid >> 1, q = tid & 1;
        const float4* ps = (const float4*)(g_P + (size_t)sSrc[row] * 256);
        const float4* pt = (const float4*)(g_P + (size_t)sTgt[row] * 256 + 128);
        const float4* bb = (const float4*)b_edge;
        float4* hd = (float4*)(hs + row * 128);
#pragma unroll
        for (int u = 0; u < 16; u++) {
            int idx = q + u * 2;
            float4 a = ps[idx], b = pt[idx], c = bb[idx];
            float4 r;
            r.x = fmaxf(a.x + b.x + c.x, 0.f);
            r.y = fmaxf(a.y + b.y + c.y, 0.f);
            r.z = fmaxf(a.z + b.z + c.z, 0.f);
            r.w = fmaxf(a.w + b.w + c.w, 0.f);
            hd[idx] = r;
        }
    }
    __syncthreads();

    // ---- scores[e,h] = (hs[e] . m[rel,h] + c[rel,h]) / sqrt(32) ----
#pragma unroll
    for (int i = 0; i < 8; i++) {
        int e = ty * 8 + i;
        int r = sRel[e];
        float p[4] = {0.f, 0.f, 0.f, 0.f};
#pragma unroll
        for (int j = 0; j < 4; j++) {
            int k = j * 32 + 2 * tx;
            float h0 = hs[e * 128 + k], h1 = hs[e * 128 + k + 1];
            float4 m0 = *(float4*)(sM + r * 512 + k * 4);
            float4 m1 = *(float4*)(sM + r * 512 + (k + 1) * 4);
            p[0] += h0 * m0.x + h1 * m1.x;
            p[1] += h0 * m0.y + h1 * m1.y;
            p[2] += h0 * m0.z + h1 * m1.z;
            p[3] += h0 * m0.w + h1 * m1.w;
        }
#pragma unroll
        for (int m = 1; m < 16; m <<= 1) {
#pragma unroll
            for (int j = 0; j < 4; j++) p[j] += __shfl_xor_sync(0xffffffffu, p[j], m);
        }
        if (tx == 0) {
#pragma unroll
            for (int j = 0; j < 4; j++)
                sSc[e * 4 + j] = (p[j] + sC[r * 4 + j]) * 0.17677669529663687f;
        }
    }

    unsigned long long acc[8][4];

    // ---- V pass (internal syncs make sSc visible to all) ----
    hs_gemm8(W_v, b_v, sW, hs, tid, tx, ty, acc);
    __syncthreads();  // all hs reads done before in-place update

    // softmax over 4 heads; hs += attn*V (in place, own columns only)
#pragma unroll
    for (int i = 0; i < 8; i++) {
        int e = ty * 8 + i;
        float s0 = sSc[e * 4 + 0], s1 = sSc[e * 4 + 1], s2 = sSc[e * 4 + 2], s3 = sSc[e * 4 + 3];
        float mx = fmaxf(fmaxf(s0, s1), fmaxf(s2, s3));
        float x0 = __expf(s0 - mx), x1 = __expf(s1 - mx), x2 = __expf(s2 - mx), x3 = __expf(s3 - mx);
        float inv = 1.f / (x0 + x1 + x2 + x3);
        float at[4] = {x0 * inv, x1 * inv, x2 * inv, x3 * inv};
#pragma unroll
        for (int j = 0; j < 4; j++) {
            int c = j * 32 + 2 * tx;
            float2 h2 = *(float2*)(hs + e * 128 + c);
            h2.x += at[j] * lo32(acc[i][j]);
            h2.y += at[j] * hi32(acc[i][j]);
            *(float2*)(hs + e * 128 + c) = h2;
        }
    }

    // ---- O1 pass, relu, dot with W_o2, reduce, store ----
    hs_gemm8(W_o1, b_o1, sW, hs, tid, tx, ty, acc);
    float bo2 = __ldg(b_o2);
    float w2lo[4], w2hi[4];
#pragma unroll
    for (int j = 0; j < 4; j++) {
        int c = j * 32 + 2 * tx;
        w2lo[j] = __ldg(W_o2 + c);
        w2hi[j] = __ldg(W_o2 + c + 1);
    }
#pragma unroll
    for (int i = 0; i < 8; i++) {
        float p = 0.f;
#pragma unroll
        for (int j = 0; j < 4; j++) {
            p = fmaf(fmaxf(lo32(acc[i][j]), 0.f), w2lo[j], p);
            p = fmaf(fmaxf(hi32(acc[i][j]), 0.f), w2hi[j], p);
        }
#pragma unroll
        for (int m = 1; m < 16; m <<= 1) p += __shfl_xor_sync(0xffffffffu, p, m);
        if (tx == 0) {
            int e = e0 + ty * 8 + i;
            if (e < E) out[e] = p + bo2;
        }
    }
}

// ---------------------------------------------------------------------------
extern "C" void kernel_launch(void* const* d_in, const int* in_sizes, int n_in,
                              void* d_out, int out_size) {
    const float* node_emb = (const float*)d_in[0];
    const int*   edge_index = (const int*)d_in[1];
    const int*   rel_type = (const int*)d_in[2];
    const float* rel_emb = (const float*)d_in[3];
    const float* W_edge = (const float*)d_in[4];
    const float* b_edge = (const float*)d_in[5];
    const float* W_q = (const float*)d_in[6];
    const float* b_q = (const float*)d_in[7];
    const float* W_k = (const float*)d_in[8];
    const float* b_k = (const float*)d_in[9];
    const float* W_v = (const float*)d_in[10];
    const float* b_v = (const float*)d_in[11];
    const float* W_o1 = (const float*)d_in[12];
    const float* b_o1 = (const float*)d_in[13];
    const float* W_o2 = (const float*)d_in[14];
    const float* b_o2 = (const float*)d_in[15];
    float* out = (float*)d_out;

    int n_nodes = in_sizes[0] / EMB;   // 100000
    int E = in_sizes[2];               // 500000

    prep_kernel<<<N_REL, 128>>>(rel_emb, W_q, b_q, W_k, b_k);

    dim3 g2((n_nodes + 127) / 128, 2);
    nodeproj_kernel<<<g2, 256>>>(node_emb, W_edge, n_nodes);

    const int SMEM3 = (128 * 128 + 32 * 128 + N_REL * 512 + N_REL * 4 + 512) * 4 + 3 * 128 * 4;
    cudaFuncSetAttribute(edge_kernel, cudaFuncAttributeMaxDynamicSharedMemorySize, SMEM3);
    edge_kernel<<<(E + 127) / 128, 256, SMEM3>>>(
        edge_index, rel_type, b_edge, W_v, b_v,
        W_o1, b_o1, W_o2, b_o2, out, E);
}

// round 5
// speedup vs baseline: 1.4731x; 1.2828x over previous
#include <cuda_runtime.h>
#include <cuda_bf16.h>
#include <cstddef>

#define EMB 256
#define HID 128
#define N_REL 10
#define LDA 136   // padded bf16 row stride (272B: bank-conflict-free fragments)

// ---------------- global scratch ----------------
__device__ float g_P[(size_t)100000 * 256];   // per-node projections
__device__ float g_M[N_REL * 128 * 4];        // folded K/Q table m[r][k][h]
__device__ float g_C[N_REL * 4];              // folded bias c[r][h]
// Pre-packed transposed weights, hi/lo bf16, padded row-major [n][LDA]
__device__ __align__(16) __nv_bfloat16 g_BvH[128 * LDA];
__device__ __align__(16) __nv_bfloat16 g_BvL[128 * LDA];
__device__ __align__(16) __nv_bfloat16 g_BoH[128 * LDA];
__device__ __align__(16) __nv_bfloat16 g_BoL[128 * LDA];
__device__ __align__(16) __nv_bfloat16 g_BeH[4 * 128 * LDA];  // [cb*2+chunk][n][LDA]
__device__ __align__(16) __nv_bfloat16 g_BeL[4 * 128 * LDA];

// ---------------- helpers ----------------
__device__ __forceinline__ void split2(float x0, float x1, unsigned& hi, unsigned& lo) {
    __nv_bfloat162 h = __floats2bfloat162_rn(x0, x1);
    float r0 = x0 - __bfloat162float(h.x);
    float r1 = x1 - __bfloat162float(h.y);
    __nv_bfloat162 l = __floats2bfloat162_rn(r0, r1);
    hi = *(unsigned*)&h;
    lo = *(unsigned*)&l;
}

__device__ __forceinline__ void mma16816(float* d, const unsigned* a, unsigned b0, unsigned b1) {
    asm volatile(
        "mma.sync.aligned.m16n8k16.row.col.f32.bf16.bf16.f32 "
        "{%0,%1,%2,%3}, {%4,%5,%6,%7}, {%8,%9}, {%0,%1,%2,%3};"
        : "+f"(d[0]), "+f"(d[1]), "+f"(d[2]), "+f"(d[3])
        : "r"(a[0]), "r"(a[1]), "r"(a[2]), "r"(a[3]), "r"(b0), "r"(b1));
}

// D[128,128] += A[128,128] @ B^T[128,128], bf16x3. Warp (wm,wn) owns m32 x n64.
__device__ __forceinline__ void gemm_bf16x3(
    const __nv_bfloat16* AHp, const __nv_bfloat16* ALp,
    const __nv_bfloat16* BHp, const __nv_bfloat16* BLp,
    int wm, int wn, int g, int tk, float d[2][8][4])
{
    for (int ks = 0; ks < 8; ks++) {
        int kb = ks * 16 + 2 * tk;
        unsigned ah[2][4], al[2][4];
#pragma unroll
        for (int t = 0; t < 2; t++) {
            int r = wm * 32 + t * 16 + g;
            ah[t][0] = *(const unsigned*)(AHp + r * LDA + kb);
            ah[t][1] = *(const unsigned*)(AHp + (r + 8) * LDA + kb);
            ah[t][2] = *(const unsigned*)(AHp + r * LDA + kb + 8);
            ah[t][3] = *(const unsigned*)(AHp + (r + 8) * LDA + kb + 8);
            al[t][0] = *(const unsigned*)(ALp + r * LDA + kb);
            al[t][1] = *(const unsigned*)(ALp + (r + 8) * LDA + kb);
            al[t][2] = *(const unsigned*)(ALp + r * LDA + kb + 8);
            al[t][3] = *(const unsigned*)(ALp + (r + 8) * LDA + kb + 8);
        }
#pragma unroll
        for (int j = 0; j < 8; j++) {
            int n = wn * 64 + j * 8 + g;
            unsigned bh0 = *(const unsigned*)(BHp + n * LDA + kb);
            unsigned bh1 = *(const unsigned*)(BHp + n * LDA + kb + 8);
            unsigned bl0 = *(const unsigned*)(BLp + n * LDA + kb);
            unsigned bl1 = *(const unsigned*)(BLp + n * LDA + kb + 8);
#pragma unroll
            for (int t = 0; t < 2; t++) {
                mma16816(d[t][j], ah[t], bh0, bh1);
                mma16816(d[t][j], ah[t], bl0, bl1);
                mma16816(d[t][j], al[t], bh0, bh1);
            }
        }
    }
}

// ---------------------------------------------------------------------------
// prep: fold Q-path through W_k (m-table) — unchanged (validated R2/R3)
// ---------------------------------------------------------------------------
__global__ void prep_kernel(const float* __restrict__ rel_emb,
                            const float* __restrict__ W_q,
                            const float* __restrict__ b_q,
                            const float* __restrict__ W_k,
                            const float* __restrict__ b_k) {
    __shared__ float qh[128];
    int r = blockIdx.x;
    int c = threadIdx.x;
    float s = b_q[c];
#pragma unroll 16
    for (int t = 0; t < 64; t++) s = fmaf(rel_emb[r * 64 + t], W_q[t * 128 + c], s);
    qh[c] = s;
    __syncthreads();
    int k = threadIdx.x;
    float m[4] = {0.f, 0.f, 0.f, 0.f};
#pragma unroll 8
    for (int d = 0; d < 32; d++)
#pragma unroll
        for (int h = 0; h < 4; h++)
            m[h] = fmaf(W_k[k * 128 + h * 32 + d], qh[h * 32 + d], m[h]);
    float4 m4 = {m[0], m[1], m[2], m[3]};
    *(float4*)(g_M + r * 512 + k * 4) = m4;
    if (k < 4) {
        float cc = 0.f;
#pragma unroll 8
        for (int d = 0; d < 32; d++) cc = fmaf(b_k[k * 32 + d], qh[k * 32 + d], cc);
        g_C[r * 4 + k] = cc;
    }
}

// ---------------------------------------------------------------------------
// packb: transposed weights -> padded hi/lo bf16 images
// ---------------------------------------------------------------------------
__global__ void packb_kernel(const float* __restrict__ Wv,
                             const float* __restrict__ Wo1,
                             const float* __restrict__ Wedge) {
    int idx = blockIdx.x * 256 + threadIdx.x;
    if (idx < 16384) {
        int n = idx & 127, k = idx >> 7;
        float x = Wv[k * 128 + n];
        __nv_bfloat16 h = __float2bfloat16(x);
        g_BvH[n * LDA + k] = h;
        g_BvL[n * LDA + k] = __float2bfloat16(x - __bfloat162float(h));
    } else if (idx < 32768) {
        int t = idx - 16384;
        int n = t & 127, k = t >> 7;
        float x = Wo1[k * 128 + n];
        __nv_bfloat16 h = __float2bfloat16(x);
        g_BoH[n * LDA + k] = h;
        g_BoL[n * LDA + k] = __float2bfloat16(x - __bfloat162float(h));
    } else if (idx < 98304) {
        int t = idx - 32768;          // 0..65535
        int cb = t >> 15;
        int r = t & 32767;
        int k = r >> 7;               // 0..255
        int n = r & 127;
        int chunk = k >> 7, kl = k & 127;
        size_t o = (size_t)((cb * 2 + chunk) * 128 + n) * LDA + kl;
        float x = Wedge[(size_t)(cb * 256 + k) * 128 + n];
        __nv_bfloat16 h = __float2bfloat16(x);
        g_BeH[o] = h;
        g_BeL[o] = __float2bfloat16(x - __bfloat162float(h));
    }
}

// ---------------------------------------------------------------------------
// nodeproj: P[n, cb*128 + :] = emb[n] @ Wedge-half, bf16x3 HMMA
// grid (782, 2), 256 threads, smem 139264B
// ---------------------------------------------------------------------------
__global__ __launch_bounds__(256) void nodeproj_kernel(const float* __restrict__ emb,
                                                       int n_nodes) {
    extern __shared__ __align__(16) char sm[];
    __nv_bfloat16* AH = (__nv_bfloat16*)sm;
    __nv_bfloat16* AL = AH + 128 * LDA;
    __nv_bfloat16* BH = AL + 128 * LDA;
    __nv_bfloat16* BL = BH + 128 * LDA;

    int tid = threadIdx.x;
    int lane = tid & 31, wid = tid >> 5;
    int g = lane >> 2, tk = lane & 3;
    int wm = wid >> 1, wn = wid & 1;
    int n0 = blockIdx.x * 128;
    int cb = blockIdx.y;

    float d[2][8][4];
#pragma unroll
    for (int t = 0; t < 2; t++)
#pragma unroll
        for (int j = 0; j < 8; j++)
#pragma unroll
            for (int c = 0; c < 4; c++) d[t][j][c] = 0.f;

    for (int chunk = 0; chunk < 2; chunk++) {
        // build A: emb[n0.., chunk*128..] split -> AH/AL
        {
            int row = tid >> 1, q = tid & 1;
            int n = n0 + row; if (n >= n_nodes) n = n_nodes - 1;
            const float4* np = (const float4*)(emb + (size_t)n * EMB + chunk * 128 + q * 64);
#pragma unroll
            for (int u = 0; u < 16; u++) {
                float4 v = np[u];
                unsigned h0, l0, h1, l1;
                split2(v.x, v.y, h0, l0);
                split2(v.z, v.w, h1, l1);
                int c = q * 64 + u * 4;
                *(unsigned*)(AH + row * LDA + c) = h0;
                *(unsigned*)(AH + row * LDA + c + 2) = h1;
                *(unsigned*)(AL + row * LDA + c) = l0;
                *(unsigned*)(AL + row * LDA + c + 2) = l1;
            }
        }
        // copy B chunk
        {
            const float4* gh = (const float4*)(g_BeH + (size_t)(cb * 2 + chunk) * 128 * LDA);
            const float4* gl = (const float4*)(g_BeL + (size_t)(cb * 2 + chunk) * 128 * LDA);
            float4* dh = (float4*)BH;
            float4* dl = (float4*)BL;
            for (int u = tid; u < 2176; u += 256) { dh[u] = gh[u]; dl[u] = gl[u]; }
        }
        __syncthreads();
        gemm_bf16x3(AH, AL, BH, BL, wm, wn, g, tk, d);
        __syncthreads();
    }
    // store D -> g_P
#pragma unroll
    for (int t = 0; t < 2; t++) {
        int lr = wm * 32 + t * 16 + g;
#pragma unroll
        for (int j = 0; j < 8; j++) {
            int col = cb * 128 + wn * 64 + j * 8 + 2 * tk;
            int n = n0 + lr;
            if (n < n_nodes) {
                float2 v = {d[t][j][0], d[t][j][1]};
                *(float2*)(g_P + (size_t)n * 256 + col) = v;
            }
            int n2 = n0 + lr + 8;
            if (n2 < n_nodes) {
                float2 v = {d[t][j][2], d[t][j][3]};
                *(float2*)(g_P + (size_t)n2 * 256 + col) = v;
            }
        }
    }
}

// ---------------------------------------------------------------------------
// edge kernel: 128 edges/block, 256 threads, bf16x3 HMMA GEMMs
// smem layout (bytes):
//   AH 0..34816, AL ..69632, BH ..104448, BL ..139264,
//   sM 139264(20480), sC 159744(160), sSc 159904(2048),
//   sSrc 161952, sTgt 162464, sRel 162976 (512 each),
//   sBv 163488, sBo 164000, sW2 164512 (512 each), sOut 165024(1024)
// total 166048
// ---------------------------------------------------------------------------
__global__ __launch_bounds__(256) void edge_kernel(
    const int* __restrict__ edge_index, const int* __restrict__ rel_type,
    const float* __restrict__ b_edge,
    const float* __restrict__ b_v, const float* __restrict__ b_o1,
    const float* __restrict__ W_o2, const float* __restrict__ b_o2,
    float* __restrict__ out, int E) {
    extern __shared__ __align__(16) char sm[];
    __nv_bfloat16* AH = (__nv_bfloat16*)sm;
    __nv_bfloat16* AL = AH + 128 * LDA;
    __nv_bfloat16* BH = AL + 128 * LDA;
    __nv_bfloat16* BL = BH + 128 * LDA;
    float* sM  = (float*)(sm + 139264);
    float* sC  = (float*)(sm + 159744);
    float* sSc = (float*)(sm + 159904);
    int* sSrc  = (int*)(sm + 161952);
    int* sTgt  = (int*)(sm + 162464);
    int* sRel  = (int*)(sm + 162976);
    float* sBv = (float*)(sm + 163488);
    float* sBo = (float*)(sm + 164000);
    float* sW2 = (float*)(sm + 164512);
    float* sOut = (float*)(sm + 165024);

    int tid = threadIdx.x;
    int lane = tid & 31, wid = tid >> 5;
    int g = lane >> 2, tk = lane & 3;
    int wm = wid >> 1, wn = wid & 1;
    int e0 = blockIdx.x * 128;

    // ---- stage ----
    for (int u = tid; u < N_REL * 512; u += 256) sM[u] = g_M[u];
    if (tid < N_REL * 4) sC[tid] = g_C[tid];
    if (tid < 128) {
        int e = e0 + tid;
        int eg = e < E ? e : E - 1;
        sSrc[tid] = edge_index[eg];
        sTgt[tid] = edge_index[E + eg];
        sRel[tid] = rel_type[eg];
        sBv[tid] = b_v[tid];
        sBo[tid] = b_o1[tid];
        sW2[tid] = W_o2[tid];
    }
    {   // Wv tiles
        const float4* gh = (const float4*)g_BvH;
        const float4* gl = (const float4*)g_BvL;
        float4* dh = (float4*)BH;
        float4* dl = (float4*)BL;
        for (int u = tid; u < 2176; u += 256) { dh[u] = gh[u]; dl[u] = gl[u]; }
    }
    __syncthreads();

    // ---- build hs = relu(P[src][0:128] + P[tgt][128:256] + b_edge), split ----
    {
        int row = tid >> 1, q = tid & 1;
        const float4* ps = (const float4*)(g_P + (size_t)sSrc[row] * 256 + q * 64);
        const float4* pt = (const float4*)(g_P + (size_t)sTgt[row] * 256 + 128 + q * 64);
        const float4* bb = (const float4*)(b_edge + q * 64);
#pragma unroll
        for (int u = 0; u < 16; u++) {
            float4 a = ps[u], b = pt[u], c = bb[u];
            float x0 = fmaxf(a.x + b.x + c.x, 0.f);
            float x1 = fmaxf(a.y + b.y + c.y, 0.f);
            float x2 = fmaxf(a.z + b.z + c.z, 0.f);
            float x3 = fmaxf(a.w + b.w + c.w, 0.f);
            unsigned h0, l0, h1, l1;
            split2(x0, x1, h0, l0);
            split2(x2, x3, h1, l1);
            int cc = q * 64 + u * 4;
            *(unsigned*)(AH + row * LDA + cc) = h0;
            *(unsigned*)(AH + row * LDA + cc + 2) = h1;
            *(unsigned*)(AL + row * LDA + cc) = l0;
            *(unsigned*)(AL + row * LDA + cc + 2) = l1;
        }
    }
    __syncthreads();

    // ---- scores: sSc[e][h] = (hs[e].m[rel,h] + c[rel,h]) / sqrt(32) ----
    {
        int tx = tid & 15, ty = tid >> 4;
#pragma unroll
        for (int i = 0; i < 8; i++) {
            int e = ty * 8 + i;
            int r = sRel[e];
            float p[4] = {0.f, 0.f, 0.f, 0.f};
#pragma unroll
            for (int j = 0; j < 4; j++) {
                int k = j * 32 + 2 * tx;
                float2 xh = __bfloat1622float2(*(const __nv_bfloat162*)(AH + e * LDA + k));
                float2 xl = __bfloat1622float2(*(const __nv_bfloat162*)(AL + e * LDA + k));
                float h0 = xh.x + xl.x, h1 = xh.y + xl.y;
                float4 m0 = *(float4*)(sM + r * 512 + k * 4);
                float4 m1 = *(float4*)(sM + r * 512 + (k + 1) * 4);
                p[0] += h0 * m0.x + h1 * m1.x;
                p[1] += h0 * m0.y + h1 * m1.y;
                p[2] += h0 * m0.z + h1 * m1.z;
                p[3] += h0 * m0.w + h1 * m1.w;
            }
#pragma unroll
            for (int m = 1; m < 16; m <<= 1)
#pragma unroll
                for (int j = 0; j < 4; j++) p[j] += __shfl_xor_sync(0xffffffffu, p[j], m);
            if (tx == 0)
#pragma unroll
                for (int j = 0; j < 4; j++)
                    sSc[e * 4 + j] = (p[j] + sC[r * 4 + j]) * 0.17677669529663687f;
        }
    }
    __syncthreads();

    // ---- GEMM1: D = hs @ Wv^T ----
    float d[2][8][4];
#pragma unroll
    for (int t = 0; t < 2; t++)
#pragma unroll
        for (int j = 0; j < 8; j++)
#pragma unroll
            for (int c = 0; c < 4; c++) d[t][j][c] = 0.f;
    gemm_bf16x3(AH, AL, BH, BL, wm, wn, g, tk, d);
    __syncthreads();

    // ---- epilogue1: softmax over heads, hs += attn*(V+b_v), re-split in place ----
#pragma unroll
    for (int t = 0; t < 2; t++) {
#pragma unroll
        for (int ch = 0; ch < 2; ch++) {
            int row = wm * 32 + t * 16 + g + ch * 8;
            float s0 = sSc[row * 4 + 0], s1 = sSc[row * 4 + 1];
            float s2 = sSc[row * 4 + 2], s3 = sSc[row * 4 + 3];
            float mx = fmaxf(fmaxf(s0, s1), fmaxf(s2, s3));
            float x0 = __expf(s0 - mx), x1 = __expf(s1 - mx);
            float x2 = __expf(s2 - mx), x3 = __expf(s3 - mx);
            float inv = 1.f / (x0 + x1 + x2 + x3);
            float at[4] = {x0 * inv, x1 * inv, x2 * inv, x3 * inv};
#pragma unroll
            for (int j = 0; j < 8; j++) {
#pragma unroll
                for (int cb2 = 0; cb2 < 2; cb2++) {
                    int col = wn * 64 + j * 8 + 2 * tk + cb2;
                    float v = d[t][j][ch * 2 + cb2] + sBv[col];
                    float x = __bfloat162float(AH[row * LDA + col]) +
                              __bfloat162float(AL[row * LDA + col]);
                    float nx = x + at[col >> 5] * v;
                    __nv_bfloat16 hh = __float2bfloat16(nx);
                    AH[row * LDA + col] = hh;
                    AL[row * LDA + col] = __float2bfloat16(nx - __bfloat162float(hh));
                }
            }
        }
    }
    // stage Wo1 tiles (GEMM1 done reading BH/BL)
    {
        const float4* gh = (const float4*)g_BoH;
        const float4* gl = (const float4*)g_BoL;
        float4* dh = (float4*)BH;
        float4* dl = (float4*)BL;
        for (int u = tid; u < 2176; u += 256) { dh[u] = gh[u]; dl[u] = gl[u]; }
    }
    __syncthreads();

    // ---- GEMM2: D2 = hs' @ Wo1^T ----
#pragma unroll
    for (int t = 0; t < 2; t++)
#pragma unroll
        for (int j = 0; j < 8; j++)
#pragma unroll
            for (int c = 0; c < 4; c++) d[t][j][c] = 0.f;
    gemm_bf16x3(AH, AL, BH, BL, wm, wn, g, tk, d);

    // ---- epilogue2: relu(D2 + b_o1) . W_o2, quad reduce, combine ----
    float pacc[2][2] = {{0.f, 0.f}, {0.f, 0.f}};
#pragma unroll
    for (int t = 0; t < 2; t++)
#pragma unroll
        for (int ch = 0; ch < 2; ch++)
#pragma unroll
            for (int j = 0; j < 8; j++)
#pragma unroll
                for (int cb2 = 0; cb2 < 2; cb2++) {
                    int col = wn * 64 + j * 8 + 2 * tk + cb2;
                    float h = fmaxf(d[t][j][ch * 2 + cb2] + sBo[col], 0.f);
                    pacc[t][ch] = fmaf(h, sW2[col], pacc[t][ch]);
                }
#pragma unroll
    for (int m = 1; m <= 2; m <<= 1)
#pragma unroll
        for (int t = 0; t < 2; t++)
#pragma unroll
            for (int ch = 0; ch < 2; ch++)
                pacc[t][ch] += __shfl_xor_sync(0xffffffffu, pacc[t][ch], m);
    if (tk == 0) {
#pragma unroll
        for (int t = 0; t < 2; t++)
#pragma unroll
            for (int ch = 0; ch < 2; ch++) {
                int row = wm * 32 + t * 16 + g + ch * 8;
                sOut[wn * 128 + row] = pacc[t][ch];
            }
    }
    __syncthreads();
    if (tid < 128) {
        int e = e0 + tid;
        if (e < E) out[e] = sOut[tid] + sOut[128 + tid] + __ldg(b_o2);
    }
}

// ---------------------------------------------------------------------------
extern "C" void kernel_launch(void* const* d_in, const int* in_sizes, int n_in,
                              void* d_out, int out_size) {
    const float* node_emb = (const float*)d_in[0];
    const int*   edge_index = (const int*)d_in[1];
    const int*   rel_type = (const int*)d_in[2];
    const float* rel_emb = (const float*)d_in[3];
    const float* W_edge = (const float*)d_in[4];
    const float* b_edge = (const float*)d_in[5];
    const float* W_q = (const float*)d_in[6];
    const float* b_q = (const float*)d_in[7];
    const float* W_k = (const float*)d_in[8];
    const float* b_k = (const float*)d_in[9];
    const float* W_v = (const float*)d_in[10];
    const float* b_v = (const float*)d_in[11];
    const float* W_o1 = (const float*)d_in[12];
    const float* b_o1 = (const float*)d_in[13];
    const float* W_o2 = (const float*)d_in[14];
    const float* b_o2 = (const float*)d_in[15];
    float* out = (float*)d_out;

    int n_nodes = in_sizes[0] / EMB;   // 100000
    int E = in_sizes[2];               // 500000

    prep_kernel<<<N_REL, 128>>>(rel_emb, W_q, b_q, W_k, b_k);
    packb_kernel<<<384, 256>>>(W_v, W_o1, W_edge);

    const int SMEM_NP = 4 * 128 * LDA * 2;     // 139264
    cudaFuncSetAttribute(nodeproj_kernel, cudaFuncAttributeMaxDynamicSharedMemorySize, SMEM_NP);
    dim3 g2((n_nodes + 127) / 128, 2);
    nodeproj_kernel<<<g2, 256, SMEM_NP>>>(node_emb, n_nodes);

    const int SMEM_E = 166048;
    cudaFuncSetAttribute(edge_kernel, cudaFuncAttributeMaxDynamicSharedMemorySize, SMEM_E);
    edge_kernel<<<(E + 127) / 128, 256, SMEM_E>>>(
        edge_index, rel_type, b_edge, b_v, b_o1, W_o2, b_o2, out, E);
}

// round 6
// speedup vs baseline: 1.6139x; 1.0956x over previous
#include <cuda_runtime.h>
#include <cuda_bf16.h>
#include <cstddef>

#define EMB 256
#define HID 128
#define N_REL 10
#define LDA 136   // padded bf16 row stride (272B: stride ≡ 4 banks → conflict-free frags)

// ---------------- global scratch ----------------
__device__ float g_P[(size_t)100000 * 256];   // per-node projections
__device__ float g_M[N_REL * 128 * 4];        // folded K/Q table m[r][k][h]
__device__ float g_C[N_REL * 4];              // folded bias c[r][h]
// Pre-packed transposed weights, hi/lo bf16, padded row-major [n][LDA]
__device__ __align__(16) __nv_bfloat16 g_BvH[128 * LDA];
__device__ __align__(16) __nv_bfloat16 g_BvL[128 * LDA];
__device__ __align__(16) __nv_bfloat16 g_BoH[128 * LDA];
__device__ __align__(16) __nv_bfloat16 g_BoL[128 * LDA];
__device__ __align__(16) __nv_bfloat16 g_BeH[4 * 128 * LDA];  // [cb*2+chunk][n][LDA]
__device__ __align__(16) __nv_bfloat16 g_BeL[4 * 128 * LDA];

// ---------------- helpers ----------------
__device__ __forceinline__ void split2(float x0, float x1, unsigned& hi, unsigned& lo) {
    __nv_bfloat162 h = __floats2bfloat162_rn(x0, x1);
    float r0 = x0 - __bfloat162float(h.x);
    float r1 = x1 - __bfloat162float(h.y);
    __nv_bfloat162 l = __floats2bfloat162_rn(r0, r1);
    hi = *(unsigned*)&h;
    lo = *(unsigned*)&l;
}

__device__ __forceinline__ void mma16816(float* d, const unsigned* a, unsigned b0, unsigned b1) {
    asm volatile(
        "mma.sync.aligned.m16n8k16.row.col.f32.bf16.bf16.f32 "
        "{%0,%1,%2,%3}, {%4,%5,%6,%7}, {%8,%9}, {%0,%1,%2,%3};"
        : "+f"(d[0]), "+f"(d[1]), "+f"(d[2]), "+f"(d[3])
        : "r"(a[0]), "r"(a[1]), "r"(a[2]), "r"(a[3]), "r"(b0), "r"(b1));
}

// D += A1@B^T + A2@B^T  (two A tiles vs one resident B tile)
__device__ __forceinline__ void gemm_2t(
    const __nv_bfloat16* A1, const __nv_bfloat16* A2, const __nv_bfloat16* B,
    int wm, int wn, int g, int tk, float d[2][8][4])
{
    for (int ks = 0; ks < 8; ks++) {
        int kb = ks * 16 + 2 * tk;
        unsigned a1[2][4], a2[2][4];
#pragma unroll
        for (int t = 0; t < 2; t++) {
            int r = wm * 32 + t * 16 + g;
            a1[t][0] = *(const unsigned*)(A1 + r * LDA + kb);
            a1[t][1] = *(const unsigned*)(A1 + (r + 8) * LDA + kb);
            a1[t][2] = *(const unsigned*)(A1 + r * LDA + kb + 8);
            a1[t][3] = *(const unsigned*)(A1 + (r + 8) * LDA + kb + 8);
            a2[t][0] = *(const unsigned*)(A2 + r * LDA + kb);
            a2[t][1] = *(const unsigned*)(A2 + (r + 8) * LDA + kb);
            a2[t][2] = *(const unsigned*)(A2 + r * LDA + kb + 8);
            a2[t][3] = *(const unsigned*)(A2 + (r + 8) * LDA + kb + 8);
        }
#pragma unroll
        for (int j = 0; j < 8; j++) {
            int n = wn * 64 + j * 8 + g;
            unsigned b0 = *(const unsigned*)(B + n * LDA + kb);
            unsigned b1 = *(const unsigned*)(B + n * LDA + kb + 8);
#pragma unroll
            for (int t = 0; t < 2; t++) {
                mma16816(d[t][j], a1[t], b0, b1);
                mma16816(d[t][j], a2[t], b0, b1);
            }
        }
    }
}

// D += A1@B^T
__device__ __forceinline__ void gemm_1t(
    const __nv_bfloat16* A1, const __nv_bfloat16* B,
    int wm, int wn, int g, int tk, float d[2][8][4])
{
    for (int ks = 0; ks < 8; ks++) {
        int kb = ks * 16 + 2 * tk;
        unsigned a1[2][4];
#pragma unroll
        for (int t = 0; t < 2; t++) {
            int r = wm * 32 + t * 16 + g;
            a1[t][0] = *(const unsigned*)(A1 + r * LDA + kb);
            a1[t][1] = *(const unsigned*)(A1 + (r + 8) * LDA + kb);
            a1[t][2] = *(const unsigned*)(A1 + r * LDA + kb + 8);
            a1[t][3] = *(const unsigned*)(A1 + (r + 8) * LDA + kb + 8);
        }
#pragma unroll
        for (int j = 0; j < 8; j++) {
            int n = wn * 64 + j * 8 + g;
            unsigned b0 = *(const unsigned*)(B + n * LDA + kb);
            unsigned b1 = *(const unsigned*)(B + n * LDA + kb + 8);
#pragma unroll
            for (int t = 0; t < 2; t++) mma16816(d[t][j], a1[t], b0, b1);
        }
    }
}

__device__ __forceinline__ void copyB(const __nv_bfloat16* src, __nv_bfloat16* dst, int tid) {
    const float4* s = (const float4*)src;
    float4* d = (float4*)dst;
    for (int u = tid; u < 2176; u += 256) d[u] = s[u];
}

// ---------------------------------------------------------------------------
// prep: fold Q-path through W_k (m-table)
// ---------------------------------------------------------------------------
__global__ void prep_kernel(const float* __restrict__ rel_emb,
                            const float* __restrict__ W_q,
                            const float* __restrict__ b_q,
                            const float* __restrict__ W_k,
                            const float* __restrict__ b_k) {
    __shared__ float qh[128];
    int r = blockIdx.x;
    int c = threadIdx.x;
    float s = b_q[c];
#pragma unroll 16
    for (int t = 0; t < 64; t++) s = fmaf(rel_emb[r * 64 + t], W_q[t * 128 + c], s);
    qh[c] = s;
    __syncthreads();
    int k = threadIdx.x;
    float m[4] = {0.f, 0.f, 0.f, 0.f};
#pragma unroll 8
    for (int d = 0; d < 32; d++)
#pragma unroll
        for (int h = 0; h < 4; h++)
            m[h] = fmaf(W_k[k * 128 + h * 32 + d], qh[h * 32 + d], m[h]);
    float4 m4 = {m[0], m[1], m[2], m[3]};
    *(float4*)(g_M + r * 512 + k * 4) = m4;
    if (k < 4) {
        float cc = 0.f;
#pragma unroll 8
        for (int d = 0; d < 32; d++) cc = fmaf(b_k[k * 32 + d], qh[k * 32 + d], cc);
        g_C[r * 4 + k] = cc;
    }
}

// ---------------------------------------------------------------------------
// packb: transposed weights -> padded hi/lo bf16 images
// ---------------------------------------------------------------------------
__global__ void packb_kernel(const float* __restrict__ Wv,
                             const float* __restrict__ Wo1,
                             const float* __restrict__ Wedge) {
    int idx = blockIdx.x * 256 + threadIdx.x;
    if (idx < 16384) {
        int n = idx & 127, k = idx >> 7;
        float x = Wv[k * 128 + n];
        __nv_bfloat16 h = __float2bfloat16(x);
        g_BvH[n * LDA + k] = h;
        g_BvL[n * LDA + k] = __float2bfloat16(x - __bfloat162float(h));
    } else if (idx < 32768) {
        int t = idx - 16384;
        int n = t & 127, k = t >> 7;
        float x = Wo1[k * 128 + n];
        __nv_bfloat16 h = __float2bfloat16(x);
        g_BoH[n * LDA + k] = h;
        g_BoL[n * LDA + k] = __float2bfloat16(x - __bfloat162float(h));
    } else if (idx < 98304) {
        int t = idx - 32768;
        int cb = t >> 15;
        int r = t & 32767;
        int k = r >> 7;
        int n = r & 127;
        int chunk = k >> 7, kl = k & 127;
        size_t o = (size_t)((cb * 2 + chunk) * 128 + n) * LDA + kl;
        float x = Wedge[(size_t)(cb * 256 + k) * 128 + n];
        __nv_bfloat16 h = __float2bfloat16(x);
        g_BeH[o] = h;
        g_BeL[o] = __float2bfloat16(x - __bfloat162float(h));
    }
}

// ---------------------------------------------------------------------------
// nodeproj: single-B-buffer, smem 104448B -> 2 blocks/SM
// ---------------------------------------------------------------------------
__global__ __launch_bounds__(256, 2) void nodeproj_kernel(const float* __restrict__ emb,
                                                          int n_nodes) {
    extern __shared__ __align__(16) char sm[];
    __nv_bfloat16* AH = (__nv_bfloat16*)sm;
    __nv_bfloat16* AL = AH + 128 * LDA;
    __nv_bfloat16* B  = AL + 128 * LDA;

    int tid = threadIdx.x;
    int lane = tid & 31, wid = tid >> 5;
    int g = lane >> 2, tk = lane & 3;
    int wm = wid >> 1, wn = wid & 1;
    int n0 = blockIdx.x * 128;
    int cb = blockIdx.y;

    float d[2][8][4];
#pragma unroll
    for (int t = 0; t < 2; t++)
#pragma unroll
        for (int j = 0; j < 8; j++)
#pragma unroll
            for (int c = 0; c < 4; c++) d[t][j][c] = 0.f;

    for (int chunk = 0; chunk < 2; chunk++) {
        __syncthreads();   // previous gemm done reading A/B
        // build A chunk
        {
            int row = tid >> 1, q = tid & 1;
            int n = n0 + row; if (n >= n_nodes) n = n_nodes - 1;
            const float4* np = (const float4*)(emb + (size_t)n * EMB + chunk * 128 + q * 64);
#pragma unroll
            for (int u = 0; u < 16; u++) {
                float4 v = np[u];
                unsigned h0, l0, h1, l1;
                split2(v.x, v.y, h0, l0);
                split2(v.z, v.w, h1, l1);
                int c = q * 64 + u * 4;
                *(unsigned*)(AH + row * LDA + c) = h0;
                *(unsigned*)(AH + row * LDA + c + 2) = h1;
                *(unsigned*)(AL + row * LDA + c) = l0;
                *(unsigned*)(AL + row * LDA + c + 2) = l1;
            }
        }
        copyB(g_BeH + (size_t)(cb * 2 + chunk) * 128 * LDA, B, tid);
        __syncthreads();
        gemm_2t(AH, AL, B, wm, wn, g, tk, d);       // Ah*Bh + Al*Bh
        __syncthreads();
        copyB(g_BeL + (size_t)(cb * 2 + chunk) * 128 * LDA, B, tid);
        __syncthreads();
        gemm_1t(AH, B, wm, wn, g, tk, d);           // Ah*Bl
    }
    // store D -> g_P
#pragma unroll
    for (int t = 0; t < 2; t++) {
        int lr = wm * 32 + t * 16 + g;
#pragma unroll
        for (int j = 0; j < 8; j++) {
            int col = cb * 128 + wn * 64 + j * 8 + 2 * tk;
            int n = n0 + lr;
            if (n < n_nodes) {
                float2 v = {d[t][j][0], d[t][j][1]};
                *(float2*)(g_P + (size_t)n * 256 + col) = v;
            }
            int n2 = n0 + lr + 8;
            if (n2 < n_nodes) {
                float2 v = {d[t][j][2], d[t][j][3]};
                *(float2*)(g_P + (size_t)n2 * 256 + col) = v;
            }
        }
    }
}

// ---------------------------------------------------------------------------
// edge kernel: single-B-buffer, smem 110592B -> 2 blocks/SM
// layout: AH 0, AL 34816, B 69632, sSc 104448, sSrc 106496, sTgt 107008,
//         sRel 107520, sBv 108032, sBo 108544, sW2 109056, sOut 109568; total 110592
// ---------------------------------------------------------------------------
__global__ __launch_bounds__(256, 2) void edge_kernel(
    const int* __restrict__ edge_index, const int* __restrict__ rel_type,
    const float* __restrict__ b_edge,
    const float* __restrict__ b_v, const float* __restrict__ b_o1,
    const float* __restrict__ W_o2, const float* __restrict__ b_o2,
    float* __restrict__ out, int E) {
    extern __shared__ __align__(16) char sm[];
    __nv_bfloat16* AH = (__nv_bfloat16*)sm;
    __nv_bfloat16* AL = AH + 128 * LDA;
    __nv_bfloat16* B  = AL + 128 * LDA;
    float* sSc = (float*)(sm + 104448);
    int* sSrc  = (int*)(sm + 106496);
    int* sTgt  = (int*)(sm + 107008);
    int* sRel  = (int*)(sm + 107520);
    float* sBv = (float*)(sm + 108032);
    float* sBo = (float*)(sm + 108544);
    float* sW2 = (float*)(sm + 109056);
    float* sOut = (float*)(sm + 109568);

    int tid = threadIdx.x;
    int lane = tid & 31, wid = tid >> 5;
    int g = lane >> 2, tk = lane & 3;
    int wm = wid >> 1, wn = wid & 1;
    int e0 = blockIdx.x * 128;

    // ---- stage indices/biases + B <- BvH ----
    if (tid < 128) {
        int e = e0 + tid;
        int eg = e < E ? e : E - 1;
        sSrc[tid] = edge_index[eg];
        sTgt[tid] = edge_index[E + eg];
        sRel[tid] = rel_type[eg];
        sBv[tid] = b_v[tid];
        sBo[tid] = b_o1[tid];
        sW2[tid] = W_o2[tid];
    }
    copyB(g_BvH, B, tid);
    __syncthreads();

    // ---- build hs = relu(P[src][0:128] + P[tgt][128:256] + b_edge), split ----
    {
        int row = tid >> 1, q = tid & 1;
        const float4* ps = (const float4*)(g_P + (size_t)sSrc[row] * 256 + q * 64);
        const float4* pt = (const float4*)(g_P + (size_t)sTgt[row] * 256 + 128 + q * 64);
        const float4* bb = (const float4*)(b_edge + q * 64);
#pragma unroll
        for (int u = 0; u < 16; u++) {
            float4 a = ps[u], b = pt[u], c = bb[u];
            float x0 = fmaxf(a.x + b.x + c.x, 0.f);
            float x1 = fmaxf(a.y + b.y + c.y, 0.f);
            float x2 = fmaxf(a.z + b.z + c.z, 0.f);
            float x3 = fmaxf(a.w + b.w + c.w, 0.f);
            unsigned h0, l0, h1, l1;
            split2(x0, x1, h0, l0);
            split2(x2, x3, h1, l1);
            int cc = q * 64 + u * 4;
            *(unsigned*)(AH + row * LDA + cc) = h0;
            *(unsigned*)(AH + row * LDA + cc + 2) = h1;
            *(unsigned*)(AL + row * LDA + cc) = l0;
            *(unsigned*)(AL + row * LDA + cc + 2) = l1;
        }
    }
    __syncthreads();

    // ---- scores: sSc[e][h] = (hs[e].m[rel,h] + c[rel,h]) / sqrt(32), m via __ldg ----
    {
        int tx = tid & 15, ty = tid >> 4;
#pragma unroll
        for (int i = 0; i < 8; i++) {
            int e = ty * 8 + i;
            int r = sRel[e];
            const float4* gm = (const float4*)(g_M + r * 512);
            float p[4] = {0.f, 0.f, 0.f, 0.f};
#pragma unroll
            for (int j = 0; j < 4; j++) {
                int k = j * 32 + 2 * tx;
                float2 xh = __bfloat1622float2(*(const __nv_bfloat162*)(AH + e * LDA + k));
                float2 xl = __bfloat1622float2(*(const __nv_bfloat162*)(AL + e * LDA + k));
                float h0 = xh.x + xl.x, h1 = xh.y + xl.y;
                float4 m0 = __ldg(gm + k);
                float4 m1 = __ldg(gm + k + 1);
                p[0] += h0 * m0.x + h1 * m1.x;
                p[1] += h0 * m0.y + h1 * m1.y;
                p[2] += h0 * m0.z + h1 * m1.z;
                p[3] += h0 * m0.w + h1 * m1.w;
            }
#pragma unroll
            for (int m = 1; m < 16; m <<= 1)
#pragma unroll
                for (int j = 0; j < 4; j++) p[j] += __shfl_xor_sync(0xffffffffu, p[j], m);
            if (tx == 0) {
                float c0 = __ldg(g_C + r * 4 + 0), c1 = __ldg(g_C + r * 4 + 1);
                float c2 = __ldg(g_C + r * 4 + 2), c3 = __ldg(g_C + r * 4 + 3);
                sSc[e * 4 + 0] = (p[0] + c0) * 0.17677669529663687f;
                sSc[e * 4 + 1] = (p[1] + c1) * 0.17677669529663687f;
                sSc[e * 4 + 2] = (p[2] + c2) * 0.17677669529663687f;
                sSc[e * 4 + 3] = (p[3] + c3) * 0.17677669529663687f;
            }
        }
    }

    // ---- GEMM1 stage1: Ah*BvH + Al*BvH ----
    float d[2][8][4];
#pragma unroll
    for (int t = 0; t < 2; t++)
#pragma unroll
        for (int j = 0; j < 8; j++)
#pragma unroll
            for (int c = 0; c < 4; c++) d[t][j][c] = 0.f;
    gemm_2t(AH, AL, B, wm, wn, g, tk, d);
    __syncthreads();
    copyB(g_BvL, B, tid);
    __syncthreads();
    gemm_1t(AH, B, wm, wn, g, tk, d);   // Ah*BvL
    __syncthreads();

    // ---- epilogue1: softmax over heads, hs += attn*(V+b_v), re-split in place;
    //      also stage B <- BoH (GEMM1 done with B) ----
#pragma unroll
    for (int t = 0; t < 2; t++) {
#pragma unroll
        for (int ch = 0; ch < 2; ch++) {
            int row = wm * 32 + t * 16 + g + ch * 8;
            float s0 = sSc[row * 4 + 0], s1 = sSc[row * 4 + 1];
            float s2 = sSc[row * 4 + 2], s3 = sSc[row * 4 + 3];
            float mx = fmaxf(fmaxf(s0, s1), fmaxf(s2, s3));
            float x0 = __expf(s0 - mx), x1 = __expf(s1 - mx);
            float x2 = __expf(s2 - mx), x3 = __expf(s3 - mx);
            float inv = 1.f / (x0 + x1 + x2 + x3);
            float at[4] = {x0 * inv, x1 * inv, x2 * inv, x3 * inv};
#pragma unroll
            for (int j = 0; j < 8; j++) {
#pragma unroll
                for (int cb2 = 0; cb2 < 2; cb2++) {
                    int col = wn * 64 + j * 8 + 2 * tk + cb2;
                    float v = d[t][j][ch * 2 + cb2] + sBv[col];
                    float x = __bfloat162float(AH[row * LDA + col]) +
                              __bfloat162float(AL[row * LDA + col]);
                    float nx = x + at[col >> 5] * v;
                    __nv_bfloat16 hh = __float2bfloat16(nx);
                    AH[row * LDA + col] = hh;
                    AL[row * LDA + col] = __float2bfloat16(nx - __bfloat162float(hh));
                }
            }
        }
    }
    copyB(g_BoH, B, tid);
    __syncthreads();

    // ---- GEMM2 ----
#pragma unroll
    for (int t = 0; t < 2; t++)
#pragma unroll
        for (int j = 0; j < 8; j++)
#pragma unroll
            for (int c = 0; c < 4; c++) d[t][j][c] = 0.f;
    gemm_2t(AH, AL, B, wm, wn, g, tk, d);
    __syncthreads();
    copyB(g_BoL, B, tid);
    __syncthreads();
    gemm_1t(AH, B, wm, wn, g, tk, d);

    // ---- epilogue2: relu(D2 + b_o1) . W_o2, quad reduce, combine ----
    float pacc[2][2] = {{0.f, 0.f}, {0.f, 0.f}};
#pragma unroll
    for (int t = 0; t < 2; t++)
#pragma unroll
        for (int ch = 0; ch < 2; ch++)
#pragma unroll
            for (int j = 0; j < 8; j++)
#pragma unroll
                for (int cb2 = 0; cb2 < 2; cb2++) {
                    int col = wn * 64 + j * 8 + 2 * tk + cb2;
                    float h = fmaxf(d[t][j][ch * 2 + cb2] + sBo[col], 0.f);
                    pacc[t][ch] = fmaf(h, sW2[col], pacc[t][ch]);
                }
#pragma unroll
    for (int m = 1; m <= 2; m <<= 1)
#pragma unroll
        for (int t = 0; t < 2; t++)
#pragma unroll
            for (int ch = 0; ch < 2; ch++)
                pacc[t][ch] += __shfl_xor_sync(0xffffffffu, pacc[t][ch], m);
    if (tk == 0) {
#pragma unroll
        for (int t = 0; t < 2; t++)
#pragma unroll
            for (int ch = 0; ch < 2; ch++) {
                int row = wm * 32 + t * 16 + g + ch * 8;
                sOut[wn * 128 + row] = pacc[t][ch];
            }
    }
    __syncthreads();
    if (tid < 128) {
        int e = e0 + tid;
        if (e < E) out[e] = sOut[tid] + sOut[128 + tid] + __ldg(b_o2);
    }
}

// ---------------------------------------------------------------------------
extern "C" void kernel_launch(void* const* d_in, const int* in_sizes, int n_in,
                              void* d_out, int out_size) {
    const float* node_emb = (const float*)d_in[0];
    const int*   edge_index = (const int*)d_in[1];
    const int*   rel_type = (const int*)d_in[2];
    const float* rel_emb = (const float*)d_in[3];
    const float* W_edge = (const float*)d_in[4];
    const float* b_edge = (const float*)d_in[5];
    const float* W_q = (const float*)d_in[6];
    const float* b_q = (const float*)d_in[7];
    const float* W_k = (const float*)d_in[8];
    const float* b_k = (const float*)d_in[9];
    const float* W_v = (const float*)d_in[10];
    const float* b_v = (const float*)d_in[11];
    const float* W_o1 = (const float*)d_in[12];
    const float* b_o1 = (const float*)d_in[13];
    const float* W_o2 = (const float*)d_in[14];
    const float* b_o2 = (const float*)d_in[15];
    float* out = (float*)d_out;

    int n_nodes = in_sizes[0] / EMB;   // 100000
    int E = in_sizes[2];               // 500000

    prep_kernel<<<N_REL, 128>>>(rel_emb, W_q, b_q, W_k, b_k);
    packb_kernel<<<384, 256>>>(W_v, W_o1, W_edge);

    const int SMEM_NP = 3 * 128 * LDA * 2;     // 104448
    cudaFuncSetAttribute(nodeproj_kernel, cudaFuncAttributeMaxDynamicSharedMemorySize, SMEM_NP);
    dim3 g2((n_nodes + 127) / 128, 2);
    nodeproj_kernel<<<g2, 256, SMEM_NP>>>(node_emb, n_nodes);

    const int SMEM_E = 110592;
    cudaFuncSetAttribute(edge_kernel, cudaFuncAttributeMaxDynamicSharedMemorySize, SMEM_E);
    edge_kernel<<<(E + 127) / 128, 256, SMEM_E>>>(
        edge_index, rel_type, b_edge, b_v, b_o1, W_o2, b_o2, out, E);
}